// round 14
// baseline (speedup 1.0000x reference)
#include <cuda_runtime.h>

#define DD 4096
#define NPAIR 2048          // float2 pairs per row
#define PLANE 2176          // 2048 + 2048/16 pad, in float2 units

__device__ float g_dev[DD];

__global__ void compute_g_kernel(const float* __restrict__ eps,
                                 const float* __restrict__ g_mu,
                                 const float* __restrict__ g_rho) {
    int i = blockIdx.x * blockDim.x + threadIdx.x;
    if (i < DD) {
        float r = g_rho[i];
        g_dev[i] = g_mu[i] + log1pf(expf(r)) * eps[i];
    }
}

// Butterfly over flat-index bit log2(H) on a 32-float register array.
template<int H>
__device__ __forceinline__ void bfly(float v[32]) {
#pragma unroll
    for (int q = 0; q < 32; q += 2*H)
#pragma unroll
        for (int j = 0; j < H; j++) {
            float a = v[q+j], b = v[q+j+H];
            v[q+j]   = a + b;
            v[q+j+H] = a - b;
        }
}

// y_row = s1 * FWHT( g * FWHT( s2 * x_row ) )
// Elements packed in float2 on elem bit 0. Flat reg index k = 2r + c:
//   c = elem bit 0, r = 4-bit register-pair index.
// Pair-space (11 bits) phase layouts, 128 threads/row (l=lane, w=warp 0..3):
//   A: regs = pair bits {0..3} (offset r),    lanes {4..8}, warps {9,10}
//   B: regs = pair bits {4..7} (offset 16r),  lanes {0..3, 8}, warps {9,10}
//   C: regs = pair bits {7..10} (offset 128r; bit 7 spectator), lanes {0..4}, warps {5,6}
// Transform coverage: P1/P5 = F over elem bits {0..4} (flat strides 1..16),
// P2/P4 = elem bits {5..8} (strides 2..16), P3 = elem bits {9..11} (strides
// 4..16) twice around the g multiply.  All factors commute.
// Pad phys(p) = p + (p>>4) (float2 units): conflict-free per 16-lane LDS.64
// half-phase for all three layouts; all offsets carry-free immediates.
// 256 threads = 2 rows per CTA (separate planes) -> barriers amortized 2x.
__global__ void __launch_bounds__(256, 4)
whvi_kernel(const float* __restrict__ x,
            const float* __restrict__ s1,
            const float* __restrict__ s2,
            float* __restrict__ out) {
    __shared__ float2 sm[2 * PLANE];   // 34816 B

    const int t = threadIdx.x;
    const int half = t >> 7;           // row within CTA
    const int u = t & 127;
    const int l = u & 31;
    const int w = u >> 5;              // 0..3

    const int plane = half * PLANE;

    const int baseA = 16*l + 512*w;
    const int baseB = (l & 15) + 256*(l >> 4) + 512*w;
    const int baseC = l + 32*w;
    const int pA = plane + baseA + (baseA >> 4);   // + r
    const int pB = plane + baseB + (baseB >> 4);   // + 17*r
    const int pC = plane + baseC + (baseC >> 4);   // + 136*r

    const int row = 2*blockIdx.x + half;
    const int elemA = 2*baseA;                     // 32 contiguous elems
    const float* xr = x + (unsigned)row * DD + elemA;

    float v[32];

    // ---- P1: coalesced load, *s2, F over elem bits {0..4} ----
#pragma unroll
    for (int q = 0; q < 8; q++) {
        float4 a = *reinterpret_cast<const float4*>(xr + 4*q);
        float4 s = *reinterpret_cast<const float4*>(s2 + elemA + 4*q);
        v[4*q+0] = a.x * s.x;
        v[4*q+1] = a.y * s.y;
        v[4*q+2] = a.z * s.z;
        v[4*q+3] = a.w * s.w;
    }
    bfly<1>(v); bfly<2>(v); bfly<4>(v); bfly<8>(v); bfly<16>(v);
#pragma unroll
    for (int r = 0; r < 16; r++)
        sm[pA + r] = make_float2(v[2*r], v[2*r+1]);
    __syncthreads();

    // ---- P2: F over elem bits {5..8} ----
#pragma unroll
    for (int r = 0; r < 16; r++) {
        float2 c = sm[pB + 17*r];
        v[2*r] = c.x; v[2*r+1] = c.y;
    }
    bfly<2>(v); bfly<4>(v); bfly<8>(v); bfly<16>(v);
#pragma unroll
    for (int r = 0; r < 16; r++)
        sm[pB + 17*r] = make_float2(v[2*r], v[2*r+1]);
    __syncthreads();

    // ---- P3: F over elem bits {9..11}, *g, F again ----
#pragma unroll
    for (int r = 0; r < 16; r++) {
        float2 c = sm[pC + 136*r];
        v[2*r] = c.x; v[2*r+1] = c.y;
    }
    bfly<4>(v); bfly<8>(v); bfly<16>(v);
#pragma unroll
    for (int r = 0; r < 16; r++) {
        float2 gv = *reinterpret_cast<const float2*>(&g_dev[2*(baseC + 128*r)]);
        v[2*r]   *= gv.x;
        v[2*r+1] *= gv.y;
    }
    bfly<4>(v); bfly<8>(v); bfly<16>(v);
#pragma unroll
    for (int r = 0; r < 16; r++)
        sm[pC + 136*r] = make_float2(v[2*r], v[2*r+1]);
    __syncthreads();

    // ---- P4: F over elem bits {5..8} ----
#pragma unroll
    for (int r = 0; r < 16; r++) {
        float2 c = sm[pB + 17*r];
        v[2*r] = c.x; v[2*r+1] = c.y;
    }
    bfly<2>(v); bfly<4>(v); bfly<8>(v); bfly<16>(v);
#pragma unroll
    for (int r = 0; r < 16; r++)
        sm[pB + 17*r] = make_float2(v[2*r], v[2*r+1]);
    __syncthreads();

    // ---- P5: F over elem bits {0..4}, *s1, coalesced store ----
#pragma unroll
    for (int r = 0; r < 16; r++) {
        float2 c = sm[pA + r];
        v[2*r] = c.x; v[2*r+1] = c.y;
    }
    bfly<1>(v); bfly<2>(v); bfly<4>(v); bfly<8>(v); bfly<16>(v);

    float* orow = out + (unsigned)row * DD + elemA;
#pragma unroll
    for (int q = 0; q < 8; q++) {
        float4 s = *reinterpret_cast<const float4*>(s1 + elemA + 4*q);
        float4 o;
        o.x = v[4*q+0] * s.x;
        o.y = v[4*q+1] * s.y;
        o.z = v[4*q+2] * s.z;
        o.w = v[4*q+3] * s.w;
        *reinterpret_cast<float4*>(orow + 4*q) = o;
    }
}

extern "C" void kernel_launch(void* const* d_in, const int* in_sizes, int n_in,
                              void* d_out, int out_size) {
    const float* x     = (const float*)d_in[0];
    const float* eps   = (const float*)d_in[1];
    const float* s1    = (const float*)d_in[2];
    const float* s2    = (const float*)d_in[3];
    const float* g_mu  = (const float*)d_in[4];
    const float* g_rho = (const float*)d_in[5];
    float* out = (float*)d_out;

    int B = in_sizes[0] / DD;   // 2048

    compute_g_kernel<<<(DD + 255) / 256, 256>>>(eps, g_mu, g_rho);
    whvi_kernel<<<B / 2, 256>>>(x, s1, s2, out);
}

// round 15
// speedup vs baseline: 1.0135x; 1.0135x over previous
#include <cuda_runtime.h>

#define DD 4096
#define SMSZ 4224   // 4096 + 4096/32 pad floats

// Scalar radix-16 FWHT over the register index (4 butterfly stages).
__device__ __forceinline__ void fwht16(float v[16]) {
#pragma unroll
    for (int s = 0; s < 4; s++) {
        const int h = 1 << s;
#pragma unroll
        for (int q = 0; q < 16; q += 2*h) {
#pragma unroll
            for (int j = 0; j < h; j++) {
                float a = v[q+j], b = v[q+j+h];
                v[q+j]   = a + b;
                v[q+j+h] = a - b;
            }
        }
    }
}

// y_row = s1 * FWHT( g * FWHT( s2 * x_row ) ),  FWHT_4096 = F_A . F_B . F_C
// (layouts identical to the 41.5us trunk):
//   Phase A: regs = bits {0..3},  lanes = bits {4..8},  warps = bits {9..11}
//   Phase B: regs = bits {4..7},  lanes = bits {0,1,2,8,9}, warps = {3,10,11}
//   Phase C: regs = bits {8..11}, lanes = bits {0..4},  warps = bits {5..7}
// Additive carry-free pad swizzle phys(i) = i + (i>>5): bank-injective per
// warp for all three layouts; every LDS/STS address is base + immediate.
// NEW vs trunk: the g-vector (g_mu + softplus(g_rho)*eps) is computed inline
// in P3 (2 MUFU + few flops per element on otherwise-idle pipes), removing
// the separate prologue kernel and its ~3us graph-node overhead.
__global__ void __launch_bounds__(256, 6)
whvi_kernel(const float* __restrict__ x,
            const float* __restrict__ s1,
            const float* __restrict__ s2,
            const float* __restrict__ eps,
            const float* __restrict__ g_mu,
            const float* __restrict__ g_rho,
            float* __restrict__ out) {
    __shared__ float sm[SMSZ];

    const int t = threadIdx.x;
    const int l = t & 31;
    const int w = t >> 5;

    const int baseA = 16*l + 512*w;
    const int baseB = (l & 7) + 8*(w & 1) + 256*(l >> 3) + 1024*(w >> 1);
    const int baseC = l + 32*w;
    const int pA = baseA + (baseA >> 5);
    const int pB = baseB + (baseB >> 5);
    const int pC = baseC + (baseC >> 5);

    const int row = blockIdx.x;
    const float* xr  = x  + (unsigned)row * DD + baseA;
    const float* s2r = s2 + baseA;

    float v[16];

    // ---- P1: coalesced load, *s2, F_A ----
#pragma unroll
    for (int q = 0; q < 4; q++) {
        float4 a = *reinterpret_cast<const float4*>(xr  + 4*q);
        float4 s = *reinterpret_cast<const float4*>(s2r + 4*q);
        v[4*q+0] = a.x * s.x;
        v[4*q+1] = a.y * s.y;
        v[4*q+2] = a.z * s.z;
        v[4*q+3] = a.w * s.w;
    }
    fwht16(v);
#pragma unroll
    for (int r = 0; r < 16; r++) sm[pA + r] = v[r];
    __syncthreads();

    // ---- P2: F_B ----  elem offset 16r -> phys offset 16r + (r>>1)
#pragma unroll
    for (int r = 0; r < 16; r++) v[r] = sm[pB + 16*r + (r >> 1)];
    fwht16(v);
#pragma unroll
    for (int r = 0; r < 16; r++) sm[pB + 16*r + (r >> 1)] = v[r];
    __syncthreads();

    // ---- P3: F_C, inline g = g_mu + softplus(g_rho)*eps, F_C ----
#pragma unroll
    for (int r = 0; r < 16; r++) v[r] = sm[pC + 264*r];
    fwht16(v);
#pragma unroll
    for (int r = 0; r < 16; r++) {
        const int i = baseC + 256*r;
        const float sp = __logf(1.0f + __expf(__ldg(&g_rho[i])));
        const float gv = fmaf(sp, __ldg(&eps[i]), __ldg(&g_mu[i]));
        v[r] *= gv;
    }
    fwht16(v);
#pragma unroll
    for (int r = 0; r < 16; r++) sm[pC + 264*r] = v[r];
    __syncthreads();

    // ---- P4: F_B ----
#pragma unroll
    for (int r = 0; r < 16; r++) v[r] = sm[pB + 16*r + (r >> 1)];
    fwht16(v);
#pragma unroll
    for (int r = 0; r < 16; r++) sm[pB + 16*r + (r >> 1)] = v[r];
    __syncthreads();

    // ---- P5: F_A, *s1, coalesced store ----
#pragma unroll
    for (int r = 0; r < 16; r++) v[r] = sm[pA + r];
    fwht16(v);

    float* orow = out + (unsigned)row * DD + baseA;
    const float* s1r = s1 + baseA;
#pragma unroll
    for (int q = 0; q < 4; q++) {
        float4 s = *reinterpret_cast<const float4*>(s1r + 4*q);
        float4 o;
        o.x = v[4*q+0] * s.x;
        o.y = v[4*q+1] * s.y;
        o.z = v[4*q+2] * s.z;
        o.w = v[4*q+3] * s.w;
        *reinterpret_cast<float4*>(orow + 4*q) = o;
    }
}

extern "C" void kernel_launch(void* const* d_in, const int* in_sizes, int n_in,
                              void* d_out, int out_size) {
    const float* x     = (const float*)d_in[0];
    const float* eps   = (const float*)d_in[1];
    const float* s1    = (const float*)d_in[2];
    const float* s2    = (const float*)d_in[3];
    const float* g_mu  = (const float*)d_in[4];
    const float* g_rho = (const float*)d_in[5];
    float* out = (float*)d_out;

    int B = in_sizes[0] / DD;   // 2048

    whvi_kernel<<<B, 256>>>(x, s1, s2, eps, g_mu, g_rho, out);
}